// round 4
// baseline (speedup 1.0000x reference)
#include <cuda_runtime.h>
#include <math_constants.h>

#define H        20
#define H3       60
#define NB       2048
#define LOUT     15
#define TSTEPS   128
#define WPAD     64      // padded W0 row (floats)

typedef unsigned long long u64;

// bias-folded, lane-interleaved W0 gather table: [V=256][64]
// slot 2l = col l, slot 2l+1 = col 30+l (l<30); slots 60..63 = 0
__device__ float W0pad[256 * WPAD];

__device__ __forceinline__ u64 pack2(float a, float b) {
    u64 r; asm("mov.b64 %0,{%1,%2};" : "=l"(r) : "f"(a), "f"(b)); return r;
}
// compiler-visible pack (no forced MOVs)
__device__ __forceinline__ u64 mk2(float a, float b) {
    float2 f = make_float2(a, b);
    return *reinterpret_cast<u64*>(&f);
}
__device__ __forceinline__ u64 ffma2(u64 a, u64 b, u64 c) {
    u64 d; asm("fma.rn.f32x2 %0,%1,%2,%3;" : "=l"(d) : "l"(a), "l"(b), "l"(c)); return d;
}
__device__ __forceinline__ void unp(u64 p, float& lo, float& hi) {
    float2 f = *reinterpret_cast<float2*>(&p);
    lo = f.x; hi = f.y;
}
__device__ __forceinline__ float tanh_fast(float x) {
    float y; asm("tanh.approx.f32 %0,%1;" : "=f"(y) : "f"(x)); return y;
}
__device__ __forceinline__ float sigm_fast(float x) {   // 0.5 + 0.5*tanh(x/2)
    return fmaf(0.5f, tanh_fast(0.5f * x), 0.5f);
}

__global__ void prep_w0(const float* __restrict__ W0, const float* __restrict__ b0i) {
    int idx = blockIdx.x * 256 + threadIdx.x;      // 16384 = 256*64
    int v = idx >> 6, sl = idx & 63;
    int l = sl >> 1;
    int c = (sl & 1) ? 30 + l : l;
    float val = 0.f;
    if (l < 30) val = W0[v * H3 + c] + b0i[c];
    W0pad[idx] = val;
}

// acc over k-pairs: lanes of the f32x2 hold (even-k sum, odd-k sum); scalar bias post-add
__device__ __forceinline__ void matvec(const u64 wa[10], const u64 wb[10],
                                       float biasA, float biasB, const u64 hp[10],
                                       float& r1, float& r2) {
    u64 aA = 0ull, aB = 0ull;
#pragma unroll
    for (int m = 0; m < 10; m++) {
        aA = ffma2(hp[m], wa[m], aA);
        aB = ffma2(hp[m], wb[m], aB);
    }
    float lo, hi;
    unp(aA, lo, hi); r1 = (lo + hi) + biasA;
    unp(aB, lo, hi); r2 = (lo + hi) + biasB;
}

__global__ void __launch_bounds__(128, 3)
gru2_kernel(const int* __restrict__ x,
            const float* __restrict__ U0, const float* __restrict__ b0r,
            const float* __restrict__ W1, const float* __restrict__ U1,
            const float* __restrict__ b1i, const float* __restrict__ b1r,
            const float* __restrict__ Wd, const float* __restrict__ bd,
            float* __restrict__ out)
{
    const unsigned F = 0xFFFFFFFFu;
    const int lane = threadIdx.x & 31;
    const int b = blockIdx.x * 4 + (threadIdx.x >> 5);   // element (grid 512 x 4 warps)
    const bool act = lane < 30;
    const int c1 = lane, c2 = act ? 30 + lane : 30;

    // ---- weights into registers: k-pair packed, cols c1/c2, 3 matrices ----
    u64 wU0a[10], wU0b[10], wW1a[10], wW1b[10], wU1a[10], wU1b[10];
#pragma unroll
    for (int m = 0; m < 10; m++) {
        int k0 = 2 * m * H3, k1 = (2 * m + 1) * H3;
        if (act) {
            wU0a[m] = pack2(U0[k0 + c1], U0[k1 + c1]);
            wU0b[m] = pack2(U0[k0 + c2], U0[k1 + c2]);
            wW1a[m] = pack2(W1[k0 + c1], W1[k1 + c1]);
            wW1b[m] = pack2(W1[k0 + c2], W1[k1 + c2]);
            wU1a[m] = pack2(U1[k0 + c1], U1[k1 + c1]);
            wU1b[m] = pack2(U1[k0 + c2], U1[k1 + c2]);
        } else {
            wU0a[m] = wU0b[m] = wW1a[m] = wW1b[m] = wU1a[m] = wU1b[m] = 0ull;
        }
    }
    const float bU0a = act ? b0r[c1] : 0.f, bU0b = act ? b0r[c2] : 0.f;
    const float bW1a = act ? b1i[c1] : 0.f, bW1b = act ? b1i[c2] : 0.f;
    const float bU1a = act ? b1r[c1] : 0.f, bU1b = act ? b1r[c2] : 0.f;

    // ---- state ----
    u64 hp0[10], hp1[10];
#pragma unroll
    for (int m = 0; m < 10; m++) { hp0[m] = 0ull; hp1[m] = 0ull; }
    float ho0 = 0.f, ho1 = 0.f;

    const int* xrow = x + b * TSTEPS;

    // software pipeline: xw pair for step t in regs, x index for t+1
    int   xi1 = __ldg(xrow + 0);
    float2 xw = *reinterpret_cast<const float2*>(W0pad + xi1 * WPAD + 2 * lane);
    xi1 = __ldg(xrow + 1);

#pragma unroll 1
    for (int t = 0; t < TSTEPS; t++) {
        // prefetch xw for t+1 and x index for t+2
        float2 xwn = *reinterpret_cast<const float2*>(W0pad + xi1 * WPAD + 2 * lane);
        xi1 = __ldg(xrow + (t + 2 < TSTEPS ? t + 2 : TSTEPS - 1));

        // rec0 = h0@U0 + b0r ; rec1 = h1@U1 + b1r
        float r0a, r0b, r1a, r1b;
        matvec(wU0a, wU0b, bU0a, bU0b, hp0, r0a, r0b);
        matvec(wU1a, wU1b, bU1a, bU1b, hp1, r1a, r1b);

        // ---- layer 0 gate exchange + gating (unit i = lane, valid i<20) ----
        {
            float s1 = xw.x + r0a;                  // z-sum for i<20; r-sum on lanes 20-29
            float s2 = xw.y + r0b;                  // r-sum on lanes 0-9 (cols 30-39); h-sums lanes 10-29
            float ra = __shfl_sync(F, s1, 20 + lane);
            float rb = __shfl_sync(F, s2, lane - 10);
            float rr = (lane < 10) ? ra : rb;
            float xh = __shfl_sync(F, xw.y, 10 + lane);
            float rh = __shfl_sync(F, r0b, 10 + lane);
            float z  = sigm_fast(s1);
            float rg = sigm_fast(rr);
            float hh = tanh_fast(fmaf(rg, rh, xh));
            ho0 = z * (ho0 - hh) + hh;
        }
        // broadcast h0_new -> hp0 (k-pair packed)
#pragma unroll
        for (int m = 0; m < 10; m++) {
            float a = __shfl_sync(F, ho0, 2 * m);
            float c = __shfl_sync(F, ho0, 2 * m + 1);
            hp0[m] = mk2(a, c);
        }

        // xw1 = h0_new @ W1 + b1i
        float q1, q2;
        matvec(wW1a, wW1b, bW1a, bW1b, hp0, q1, q2);

        // ---- layer 1 gate exchange + gating ----
        {
            float s1 = q1 + r1a;
            float s2 = q2 + r1b;
            float ra = __shfl_sync(F, s1, 20 + lane);
            float rb = __shfl_sync(F, s2, lane - 10);
            float rr = (lane < 10) ? ra : rb;
            float xh = __shfl_sync(F, q2, 10 + lane);
            float rh = __shfl_sync(F, r1b, 10 + lane);
            float z  = sigm_fast(s1);
            float rg = sigm_fast(rr);
            float hh = tanh_fast(fmaf(rg, rh, xh));
            ho1 = z * (ho1 - hh) + hh;
        }
#pragma unroll
        for (int m = 0; m < 10; m++) {
            float a = __shfl_sync(F, ho1, 2 * m);
            float c = __shfl_sync(F, ho1, 2 * m + 1);
            hp1[m] = mk2(a, c);
        }

        xw = xwn;
    }

    // ---- logits = softmax(h1 @ Wd + bd) ; lane c<15 owns logit c ----
    float lg = -CUDART_INF_F;
    if (lane < LOUT) {
        lg = bd[lane];
#pragma unroll
        for (int m = 0; m < 10; m++) {
            float ha, hb;
            unp(hp1[m], ha, hb);
            lg = fmaf(ha, Wd[(2 * m) * LOUT + lane], lg);
            lg = fmaf(hb, Wd[(2 * m + 1) * LOUT + lane], lg);
        }
    }
    // reductions over the 16-lane group (lanes 0-15; lane 15 holds -inf)
    float mx = lg;
#pragma unroll
    for (int d = 8; d >= 1; d >>= 1) mx = fmaxf(mx, __shfl_xor_sync(F, mx, d));
    float p = __expf(lg - mx);
    float sm = p;
#pragma unroll
    for (int d = 8; d >= 1; d >>= 1) sm += __shfl_xor_sync(F, sm, d);
    if (lane < LOUT) out[b * LOUT + lane] = __fdividef(p, sm);
}

extern "C" void kernel_launch(void* const* d_in, const int* in_sizes, int n_in,
                              void* d_out, int out_size) {
    const int*   x   = (const int*)d_in[0];
    const float* W0  = (const float*)d_in[1];
    const float* U0  = (const float*)d_in[2];
    const float* b0i = (const float*)d_in[3];
    const float* b0r = (const float*)d_in[4];
    const float* W1  = (const float*)d_in[5];
    const float* U1  = (const float*)d_in[6];
    const float* b1i = (const float*)d_in[7];
    const float* b1r = (const float*)d_in[8];
    const float* Wd  = (const float*)d_in[9];
    const float* bd  = (const float*)d_in[10];
    // d_in[11] = drop_rate (identity), unused

    prep_w0<<<64, 256>>>(W0, b0i);
    gru2_kernel<<<NB / 4, 128>>>(x, U0, b0r, W1, U1, b1i, b1r, Wd, bd, (float*)d_out);
}

// round 7
// speedup vs baseline: 1.1365x; 1.1365x over previous
#include <cuda_runtime.h>
#include <math_constants.h>

#define H        20
#define H3       60
#define NB       2048
#define LOUT     15
#define TSTEPS   128
#define WPAD     64      // padded W0 row (floats)

typedef unsigned long long u64;

// bias-folded, lane-interleaved W0 gather table: [V=256][64]
// slot 2l = col l, slot 2l+1 = col 30+l (l<30); slots 60..63 = 0
__device__ float W0pad[256 * WPAD];

__device__ __forceinline__ u64 pack2(float a, float b) {
    u64 r; asm("mov.b64 %0,{%1,%2};" : "=l"(r) : "f"(a), "f"(b)); return r;
}
__device__ __forceinline__ u64 mk2(float a, float b) {
    float2 f = make_float2(a, b);
    return *reinterpret_cast<u64*>(&f);
}
__device__ __forceinline__ u64 ffma2(u64 a, u64 b, u64 c) {
    u64 d; asm("fma.rn.f32x2 %0,%1,%2,%3;" : "=l"(d) : "l"(a), "l"(b), "l"(c)); return d;
}
__device__ __forceinline__ void unp(u64 p, float& lo, float& hi) {
    float2 f = *reinterpret_cast<float2*>(&p);
    lo = f.x; hi = f.y;
}
__device__ __forceinline__ float tanh_fast(float x) {
    float y; asm("tanh.approx.f32 %0,%1;" : "=f"(y) : "f"(x)); return y;
}
__device__ __forceinline__ float sigm_fast(float x) {   // 0.5 + 0.5*tanh(x/2)
    return fmaf(0.5f, tanh_fast(0.5f * x), 0.5f);
}

__global__ void prep_w0(const float* __restrict__ W0, const float* __restrict__ b0i) {
    int idx = blockIdx.x * 256 + threadIdx.x;      // 16384 = 256*64
    int v = idx >> 6, sl = idx & 63;
    int l = sl >> 1;
    int c = (sl & 1) ? 30 + l : l;
    float val = 0.f;
    if (l < 30) val = W0[v * H3 + c] + b0i[c];
    W0pad[idx] = val;
}

// acc over k-pairs; scalar bias post-add
__device__ __forceinline__ void matvec(const u64 wa[10], const u64 wb[10],
                                       float biasA, float biasB, const u64 hp[10],
                                       float& r1, float& r2) {
    u64 aA = 0ull, aB = 0ull;
#pragma unroll
    for (int m = 0; m < 10; m++) {
        aA = ffma2(hp[m], wa[m], aA);
        aB = ffma2(hp[m], wb[m], aB);
    }
    float lo, hi;
    unp(aA, lo, hi); r1 = (lo + hi) + biasA;
    unp(aB, lo, hi); r2 = (lo + hi) + biasB;
}

// one GRU gate-exchange + update for a 2-col-per-lane layout
__device__ __forceinline__ void gates(float s1_in, float s2_in, float x2, float r2v,
                                      int lane, float& ho) {
    const unsigned F = 0xFFFFFFFFu;
    float s1 = s1_in;                       // z-sum on lanes<20; r-sum lanes 20-29
    float s2 = s2_in;                       // r-sum lanes 0-9; h-sums lanes 10-29
    float ra = __shfl_sync(F, s1, 20 + lane);
    float rb = __shfl_sync(F, s2, lane - 10);
    float rr = (lane < 10) ? ra : rb;
    float xh = __shfl_sync(F, x2, 10 + lane);
    float rh = __shfl_sync(F, r2v, 10 + lane);
    float z  = sigm_fast(s1);
    float rg = sigm_fast(rr);
    float hh = tanh_fast(fmaf(rg, rh, xh));
    ho = z * (ho - hh) + hh;
}

__device__ __forceinline__ void bcast(float ho, u64 hp[10]) {
    const unsigned F = 0xFFFFFFFFu;
#pragma unroll
    for (int m = 0; m < 10; m++) {
        float a = __shfl_sync(F, ho, 2 * m);
        float c = __shfl_sync(F, ho, 2 * m + 1);
        hp[m] = mk2(a, c);
    }
}

__global__ void __launch_bounds__(128, 2)
gru2_kernel(const int* __restrict__ x,
            const float* __restrict__ U0, const float* __restrict__ b0r,
            const float* __restrict__ W1, const float* __restrict__ U1,
            const float* __restrict__ b1i, const float* __restrict__ b1r,
            const float* __restrict__ Wd, const float* __restrict__ bd,
            float* __restrict__ out)
{
    const unsigned F = 0xFFFFFFFFu;
    const int lane = threadIdx.x & 31;
    const int e0 = (blockIdx.x * 4 + (threadIdx.x >> 5)) * 2;  // two elements per warp
    const bool act = lane < 30;
    const int c1 = lane, c2 = act ? 30 + lane : 30;

    // ---- weights into registers (shared by both elements) ----
    u64 wU0a[10], wU0b[10], wW1a[10], wW1b[10], wU1a[10], wU1b[10];
#pragma unroll
    for (int m = 0; m < 10; m++) {
        int k0 = 2 * m * H3, k1 = (2 * m + 1) * H3;
        if (act) {
            wU0a[m] = pack2(U0[k0 + c1], U0[k1 + c1]);
            wU0b[m] = pack2(U0[k0 + c2], U0[k1 + c2]);
            wW1a[m] = pack2(W1[k0 + c1], W1[k1 + c1]);
            wW1b[m] = pack2(W1[k0 + c2], W1[k1 + c2]);
            wU1a[m] = pack2(U1[k0 + c1], U1[k1 + c1]);
            wU1b[m] = pack2(U1[k0 + c2], U1[k1 + c2]);
        } else {
            wU0a[m] = wU0b[m] = wW1a[m] = wW1b[m] = wU1a[m] = wU1b[m] = 0ull;
        }
    }
    const float bU0a = act ? b0r[c1] : 0.f, bU0b = act ? b0r[c2] : 0.f;
    const float bW1a = act ? b1i[c1] : 0.f, bW1b = act ? b1i[c2] : 0.f;
    const float bU1a = act ? b1r[c1] : 0.f, bU1b = act ? b1r[c2] : 0.f;

    // ---- state: two independent elements A,B ----
    u64 hA0[10], hA1[10], hB0[10], hB1[10];
#pragma unroll
    for (int m = 0; m < 10; m++) { hA0[m] = hA1[m] = hB0[m] = hB1[m] = 0ull; }
    float hoA0 = 0.f, hoA1 = 0.f, hoB0 = 0.f, hoB1 = 0.f;

    const int* xrowA = x + e0 * TSTEPS;
    const int* xrowB = xrowA + TSTEPS;

    int xiA = __ldg(xrowA + 0), xiB = __ldg(xrowB + 0);
    float2 xwA = *reinterpret_cast<const float2*>(W0pad + xiA * WPAD + 2 * lane);
    float2 xwB = *reinterpret_cast<const float2*>(W0pad + xiB * WPAD + 2 * lane);
    xiA = __ldg(xrowA + 1); xiB = __ldg(xrowB + 1);

#pragma unroll 1
    for (int t = 0; t < TSTEPS; t++) {
        float2 xwnA = *reinterpret_cast<const float2*>(W0pad + xiA * WPAD + 2 * lane);
        float2 xwnB = *reinterpret_cast<const float2*>(W0pad + xiB * WPAD + 2 * lane);
        int tn = (t + 2 < TSTEPS) ? t + 2 : TSTEPS - 1;
        xiA = __ldg(xrowA + tn); xiB = __ldg(xrowB + tn);

        // recurrent matvecs (4 independent chains)
        float r0aA, r0bA, r1aA, r1bA, r0aB, r0bB, r1aB, r1bB;
        matvec(wU0a, wU0b, bU0a, bU0b, hA0, r0aA, r0bA);
        matvec(wU0a, wU0b, bU0a, bU0b, hB0, r0aB, r0bB);
        matvec(wU1a, wU1b, bU1a, bU1b, hA1, r1aA, r1bA);
        matvec(wU1a, wU1b, bU1a, bU1b, hB1, r1aB, r1bB);

        // layer-0 gates + h0 broadcast
        gates(xwA.x + r0aA, xwA.y + r0bA, xwA.y, r0bA, lane, hoA0);
        gates(xwB.x + r0aB, xwB.y + r0bB, xwB.y, r0bB, lane, hoB0);
        bcast(hoA0, hA0);
        bcast(hoB0, hB0);

        // xw1 = h0_new @ W1 + b1i, then layer-1 gates
        float q1A, q2A, q1B, q2B;
        matvec(wW1a, wW1b, bW1a, bW1b, hA0, q1A, q2A);
        matvec(wW1a, wW1b, bW1a, bW1b, hB0, q1B, q2B);
        gates(q1A + r1aA, q2A + r1bA, q2A, r1bA, lane, hoA1);
        gates(q1B + r1aB, q2B + r1bB, q2B, r1bB, lane, hoB1);
        bcast(hoA1, hA1);
        bcast(hoB1, hB1);

        xwA = xwnA; xwB = xwnB;
    }

    // ---- softmax(h1 @ Wd + bd) per element; lane c<15 owns logit c ----
#pragma unroll
    for (int el = 0; el < 2; el++) {
        const u64* hp = el ? hB1 : hA1;
        float lg = -CUDART_INF_F;
        if (lane < LOUT) {
            lg = bd[lane];
#pragma unroll
            for (int m = 0; m < 10; m++) {
                float ha, hb;
                unp(hp[m], ha, hb);
                lg = fmaf(ha, Wd[(2 * m) * LOUT + lane], lg);
                lg = fmaf(hb, Wd[(2 * m + 1) * LOUT + lane], lg);
            }
        }
        float mx = lg;
#pragma unroll
        for (int d = 8; d >= 1; d >>= 1) mx = fmaxf(mx, __shfl_xor_sync(F, mx, d));
        float p = __expf(lg - mx);
        float sm = p;
#pragma unroll
        for (int d = 8; d >= 1; d >>= 1) sm += __shfl_xor_sync(F, sm, d);
        if (lane < LOUT) out[(e0 + el) * LOUT + lane] = __fdividef(p, sm);
    }
}

extern "C" void kernel_launch(void* const* d_in, const int* in_sizes, int n_in,
                              void* d_out, int out_size) {
    const int*   x   = (const int*)d_in[0];
    const float* W0  = (const float*)d_in[1];
    const float* U0  = (const float*)d_in[2];
    const float* b0i = (const float*)d_in[3];
    const float* b0r = (const float*)d_in[4];
    const float* W1  = (const float*)d_in[5];
    const float* U1  = (const float*)d_in[6];
    const float* b1i = (const float*)d_in[7];
    const float* b1r = (const float*)d_in[8];
    const float* Wd  = (const float*)d_in[9];
    const float* bd  = (const float*)d_in[10];
    // d_in[11] = drop_rate (identity), unused

    prep_w0<<<64, 256>>>(W0, b0i);
    gru2_kernel<<<NB / 8, 128>>>(x, U0, b0r, W1, U1, b1i, b1r, Wd, bd, (float*)d_out);
}

// round 9
// speedup vs baseline: 1.2851x; 1.1308x over previous
#include <cuda_runtime.h>
#include <math_constants.h>

#define H        20
#define H3       60
#define NB       2048
#define LOUT     15
#define TSTEPS   128
#define WPAD     64      // padded W0 row (floats)

typedef unsigned long long u64;

// bias-folded, lane-interleaved W0 gather table: [V=256][64]
// slot 2l = col l, slot 2l+1 = col 30+l (l<30); slots 60..63 = 0
__device__ float W0pad[256 * WPAD];

__device__ __forceinline__ u64 pack2(float a, float b) {
    u64 r; asm("mov.b64 %0,{%1,%2};" : "=l"(r) : "f"(a), "f"(b)); return r;
}
__device__ __forceinline__ u64 mk2(float a, float b) {
    float2 f = make_float2(a, b);
    return *reinterpret_cast<u64*>(&f);
}
__device__ __forceinline__ u64 ffma2(u64 a, u64 b, u64 c) {
    u64 d; asm("fma.rn.f32x2 %0,%1,%2,%3;" : "=l"(d) : "l"(a), "l"(b), "l"(c)); return d;
}
__device__ __forceinline__ void unp(u64 p, float& lo, float& hi) {
    float2 f = *reinterpret_cast<float2*>(&p);
    lo = f.x; hi = f.y;
}
__device__ __forceinline__ float tanh_fast(float x) {
    float y; asm("tanh.approx.f32 %0,%1;" : "=f"(y) : "f"(x)); return y;
}
__device__ __forceinline__ float sigm_fast(float x) {   // 0.5 + 0.5*tanh(x/2)
    return fmaf(0.5f, tanh_fast(0.5f * x), 0.5f);
}

__global__ void prep_w0(const float* __restrict__ W0, const float* __restrict__ b0i) {
    int idx = blockIdx.x * 256 + threadIdx.x;      // 16384 = 256*64
    int v = idx >> 6, sl = idx & 63;
    int l = sl >> 1;
    int c = (sl & 1) ? 30 + l : l;
    float val = 0.f;
    if (l < 30) val = W0[v * H3 + c] + b0i[c];
    W0pad[idx] = val;
}

// acc over k-pairs; scalar bias post-add
__device__ __forceinline__ void matvec(const u64 wa[10], const u64 wb[10],
                                       float biasA, float biasB, const u64 hp[10],
                                       float& r1, float& r2) {
    u64 aA = 0ull, aB = 0ull;
#pragma unroll
    for (int m = 0; m < 10; m++) {
        aA = ffma2(hp[m], wa[m], aA);
        aB = ffma2(hp[m], wb[m], aB);
    }
    float lo, hi;
    unp(aA, lo, hi); r1 = (lo + hi) + biasA;
    unp(aB, lo, hi); r2 = (lo + hi) + biasB;
}

// one GRU gate-exchange + update for the 2-col-per-lane layout (unit i = lane, i<20)
__device__ __forceinline__ void gates(float s1, float s2, float x2, float r2v,
                                      int lane, float& ho) {
    const unsigned F = 0xFFFFFFFFu;
    float ra = __shfl_sync(F, s1, 20 + lane);
    float rb = __shfl_sync(F, s2, lane - 10);
    float rr = (lane < 10) ? ra : rb;
    float xh = __shfl_sync(F, x2, 10 + lane);
    float rh = __shfl_sync(F, r2v, 10 + lane);
    float z  = sigm_fast(s1);
    float rg = sigm_fast(rr);
    float hh = tanh_fast(fmaf(rg, rh, xh));
    ho = z * (ho - hh) + hh;
}

// SMEM broadcast reload: 20 floats -> 10 k-pair u64 via 5x LDS.128
__device__ __forceinline__ void ld_h(const float* __restrict__ p, u64 hp[10]) {
#pragma unroll
    for (int i = 0; i < 5; i++) {
        float4 f = *reinterpret_cast<const float4*>(p + 4 * i);
        hp[2 * i]     = mk2(f.x, f.y);
        hp[2 * i + 1] = mk2(f.z, f.w);
    }
}

__global__ void __launch_bounds__(128, 2)
gru2_kernel(const int* __restrict__ x,
            const float* __restrict__ U0, const float* __restrict__ b0r,
            const float* __restrict__ W1, const float* __restrict__ U1,
            const float* __restrict__ b1i, const float* __restrict__ b1r,
            const float* __restrict__ Wd, const float* __restrict__ bd,
            float* __restrict__ out)
{
    __shared__ __align__(16) float hsm[4][2][2][20];   // [warp][elem][layer][unit]

    const unsigned F = 0xFFFFFFFFu;
    const int lane = threadIdx.x & 31;
    const int w = threadIdx.x >> 5;
    const int e0 = (blockIdx.x * 4 + w) * 2;           // two elements per warp
    const bool act = lane < 30;
    const int c1 = lane, c2 = act ? 30 + lane : 30;

    float* hA0s = &hsm[w][0][0][0];
    float* hB0s = &hsm[w][1][0][0];
    float* hA1s = &hsm[w][0][1][0];
    float* hB1s = &hsm[w][1][1][0];

    // ---- weights into registers (shared by both elements) ----
    u64 wU0a[10], wU0b[10], wW1a[10], wW1b[10], wU1a[10], wU1b[10];
#pragma unroll
    for (int m = 0; m < 10; m++) {
        int k0 = 2 * m * H3, k1 = (2 * m + 1) * H3;
        if (act) {
            wU0a[m] = pack2(U0[k0 + c1], U0[k1 + c1]);
            wU0b[m] = pack2(U0[k0 + c2], U0[k1 + c2]);
            wW1a[m] = pack2(W1[k0 + c1], W1[k1 + c1]);
            wW1b[m] = pack2(W1[k0 + c2], W1[k1 + c2]);
            wU1a[m] = pack2(U1[k0 + c1], U1[k1 + c1]);
            wU1b[m] = pack2(U1[k0 + c2], U1[k1 + c2]);
        } else {
            wU0a[m] = wU0b[m] = wW1a[m] = wW1b[m] = wU1a[m] = wU1b[m] = 0ull;
        }
    }
    const float bU0a = act ? b0r[c1] : 0.f, bU0b = act ? b0r[c2] : 0.f;
    const float bW1a = act ? b1i[c1] : 0.f, bW1b = act ? b1i[c2] : 0.f;
    const float bU1a = act ? b1r[c1] : 0.f, bU1b = act ? b1r[c2] : 0.f;

    // ---- state: two independent elements A,B ----
    u64 hpA0[10], hpA1[10], hpB0[10], hpB1[10];
#pragma unroll
    for (int m = 0; m < 10; m++) { hpA0[m] = hpA1[m] = hpB0[m] = hpB1[m] = 0ull; }
    float hoA0 = 0.f, hoA1 = 0.f, hoB0 = 0.f, hoB1 = 0.f;

    const int* xrowA = x + e0 * TSTEPS;
    const int* xrowB = xrowA + TSTEPS;

    int xiA = __ldg(xrowA + 0), xiB = __ldg(xrowB + 0);
    float2 xwA = *reinterpret_cast<const float2*>(W0pad + xiA * WPAD + 2 * lane);
    float2 xwB = *reinterpret_cast<const float2*>(W0pad + xiB * WPAD + 2 * lane);
    xiA = __ldg(xrowA + 1); xiB = __ldg(xrowB + 1);

#pragma unroll 1
    for (int t = 0; t < TSTEPS; t++) {
        float2 xwnA = *reinterpret_cast<const float2*>(W0pad + xiA * WPAD + 2 * lane);
        float2 xwnB = *reinterpret_cast<const float2*>(W0pad + xiB * WPAD + 2 * lane);
        int tn = (t + 2 < TSTEPS) ? t + 2 : TSTEPS - 1;
        xiA = __ldg(xrowA + tn); xiB = __ldg(xrowB + tn);

        // recurrent matvecs (4 independent chains)
        float r0aA, r0bA, r1aA, r1bA, r0aB, r0bB, r1aB, r1bB;
        matvec(wU0a, wU0b, bU0a, bU0b, hpA0, r0aA, r0bA);
        matvec(wU0a, wU0b, bU0a, bU0b, hpB0, r0aB, r0bB);
        matvec(wU1a, wU1b, bU1a, bU1b, hpA1, r1aA, r1bA);
        matvec(wU1a, wU1b, bU1a, bU1b, hpB1, r1aB, r1bB);

        // layer-0 gates; publish h0 via SMEM broadcast
        gates(xwA.x + r0aA, xwA.y + r0bA, xwA.y, r0bA, lane, hoA0);
        gates(xwB.x + r0aB, xwB.y + r0bB, xwB.y, r0bB, lane, hoB0);
        if (lane < H) { hA0s[lane] = hoA0; hB0s[lane] = hoB0; }
        __syncwarp();
        ld_h(hA0s, hpA0);
        ld_h(hB0s, hpB0);

        // xw1 = h0_new @ W1 + b1i, then layer-1 gates
        float q1A, q2A, q1B, q2B;
        matvec(wW1a, wW1b, bW1a, bW1b, hpA0, q1A, q2A);
        matvec(wW1a, wW1b, bW1a, bW1b, hpB0, q1B, q2B);
        gates(q1A + r1aA, q2A + r1bA, q2A, r1bA, lane, hoA1);
        gates(q1B + r1aB, q2B + r1bB, q2B, r1bB, lane, hoB1);
        if (lane < H) { hA1s[lane] = hoA1; hB1s[lane] = hoB1; }
        __syncwarp();
        ld_h(hA1s, hpA1);
        ld_h(hB1s, hpB1);

        xwA = xwnA; xwB = xwnB;
    }

    // ---- softmax(h1 @ Wd + bd) per element; lane c<15 owns logit c ----
#pragma unroll
    for (int el = 0; el < 2; el++) {
        const u64* hp = el ? hpB1 : hpA1;
        float lg = -CUDART_INF_F;
        if (lane < LOUT) {
            lg = bd[lane];
#pragma unroll
            for (int m = 0; m < 10; m++) {
                float ha, hb;
                unp(hp[m], ha, hb);
                lg = fmaf(ha, Wd[(2 * m) * LOUT + lane], lg);
                lg = fmaf(hb, Wd[(2 * m + 1) * LOUT + lane], lg);
            }
        }
        float mx = lg;
#pragma unroll
        for (int d = 8; d >= 1; d >>= 1) mx = fmaxf(mx, __shfl_xor_sync(F, mx, d));
        float p = __expf(lg - mx);
        float sm = p;
#pragma unroll
        for (int d = 8; d >= 1; d >>= 1) sm += __shfl_xor_sync(F, sm, d);
        if (lane < LOUT) out[(e0 + el) * LOUT + lane] = __fdividef(p, sm);
    }
}

extern "C" void kernel_launch(void* const* d_in, const int* in_sizes, int n_in,
                              void* d_out, int out_size) {
    const int*   x   = (const int*)d_in[0];
    const float* W0  = (const float*)d_in[1];
    const float* U0  = (const float*)d_in[2];
    const float* b0i = (const float*)d_in[3];
    const float* b0r = (const float*)d_in[4];
    const float* W1  = (const float*)d_in[5];
    const float* U1  = (const float*)d_in[6];
    const float* b1i = (const float*)d_in[7];
    const float* b1r = (const float*)d_in[8];
    const float* Wd  = (const float*)d_in[9];
    const float* bd  = (const float*)d_in[10];
    // d_in[11] = drop_rate (identity), unused

    prep_w0<<<64, 256>>>(W0, b0i);
    gru2_kernel<<<NB / 8, 128>>>(x, U0, b0r, W1, U1, b1i, b1r, Wd, bd, (float*)d_out);
}

// round 14
// speedup vs baseline: 1.2930x; 1.0061x over previous
#include <cuda_runtime.h>
#include <math_constants.h>

#define H        20
#define H3       60
#define NB       2048
#define LOUT     15
#define TSTEPS   128
#define WPAD     64      // padded W0 row (floats)

typedef unsigned long long u64;

// bias-folded, lane-interleaved W0 gather table: [V=256][64]
// slot 2l = col l, slot 2l+1 = col 30+l (l<30); slots 60..63 = 0
__device__ float W0pad[256 * WPAD];

__device__ __forceinline__ u64 pack2(float a, float b) {
    u64 r; asm("mov.b64 %0,{%1,%2};" : "=l"(r) : "f"(a), "f"(b)); return r;
}
__device__ __forceinline__ u64 mk2(float a, float b) {
    float2 f = make_float2(a, b);
    return *reinterpret_cast<u64*>(&f);
}
__device__ __forceinline__ u64 ffma2(u64 a, u64 b, u64 c) {
    u64 d; asm("fma.rn.f32x2 %0,%1,%2,%3;" : "=l"(d) : "l"(a), "l"(b), "l"(c)); return d;
}
__device__ __forceinline__ void unp(u64 p, float& lo, float& hi) {
    float2 f = *reinterpret_cast<float2*>(&p);
    lo = f.x; hi = f.y;
}
__device__ __forceinline__ float tanh_fast(float x) {
    float y; asm("tanh.approx.f32 %0,%1;" : "=f"(y) : "f"(x)); return y;
}
__device__ __forceinline__ float sigm_fast(float x) {   // 0.5 + 0.5*tanh(x/2)
    return fmaf(0.5f, tanh_fast(0.5f * x), 0.5f);
}

__global__ void prep_w0(const float* __restrict__ W0, const float* __restrict__ b0i) {
    int idx = blockIdx.x * 256 + threadIdx.x;      // 16384 = 256*64
    int v = idx >> 6, sl = idx & 63;
    int l = sl >> 1;
    int c = (sl & 1) ? 30 + l : l;
    float val = 0.f;
    if (l < 30) val = W0[v * H3 + c] + b0i[c];
    W0pad[idx] = val;
}

// acc over k-pairs; scalar bias post-add
__device__ __forceinline__ void matvec(const u64 wa[10], const u64 wb[10],
                                       float biasA, float biasB, const u64 hp[10],
                                       float& r1, float& r2) {
    u64 aA = 0ull, aB = 0ull;
#pragma unroll
    for (int m = 0; m < 10; m++) {
        aA = ffma2(hp[m], wa[m], aA);
        aB = ffma2(hp[m], wb[m], aB);
    }
    float lo, hi;
    unp(aA, lo, hi); r1 = (lo + hi) + biasA;
    unp(aB, lo, hi); r2 = (lo + hi) + biasB;
}

// one GRU gate-exchange + update for the 2-col-per-lane layout (unit i = lane, i<20)
__device__ __forceinline__ void gates(float s1, float s2, float x2, float r2v,
                                      int lane, float& ho) {
    const unsigned F = 0xFFFFFFFFu;
    float ra = __shfl_sync(F, s1, 20 + lane);
    float rb = __shfl_sync(F, s2, lane - 10);
    float rr = (lane < 10) ? ra : rb;
    float xh = __shfl_sync(F, x2, 10 + lane);
    float rh = __shfl_sync(F, r2v, 10 + lane);
    float z  = sigm_fast(s1);
    float rg = sigm_fast(rr);
    float hh = tanh_fast(fmaf(rg, rh, xh));
    ho = z * (ho - hh) + hh;
}

// SMEM broadcast reload: 20 floats -> 10 k-pair u64 via 5x LDS.128
__device__ __forceinline__ void ld_h(const float* __restrict__ p, u64 hp[10]) {
#pragma unroll
    for (int i = 0; i < 5; i++) {
        float4 f = *reinterpret_cast<const float4*>(p + 4 * i);
        hp[2 * i]     = mk2(f.x, f.y);
        hp[2 * i + 1] = mk2(f.z, f.w);
    }
}

__global__ void __launch_bounds__(128, 2)
gru2_kernel(const int* __restrict__ x,
            const float* __restrict__ U0, const float* __restrict__ b0r,
            const float* __restrict__ W1, const float* __restrict__ U1,
            const float* __restrict__ b1i, const float* __restrict__ b1r,
            const float* __restrict__ Wd, const float* __restrict__ bd,
            float* __restrict__ out)
{
    __shared__ __align__(16) float hsm[4][2][2][20];   // [warp][elem][layer][unit]

    const unsigned F = 0xFFFFFFFFu;
    const int lane = threadIdx.x & 31;
    const int w = threadIdx.x >> 5;
    const int e0 = (blockIdx.x * 4 + w) * 2;           // two elements per warp
    const bool act = lane < 30;
    const int c1 = lane, c2 = act ? 30 + lane : 30;

    float* hA0s = &hsm[w][0][0][0];
    float* hB0s = &hsm[w][1][0][0];
    float* hA1s = &hsm[w][0][1][0];
    float* hB1s = &hsm[w][1][1][0];

    // ---- weights into registers (shared by both elements) ----
    u64 wU0a[10], wU0b[10], wW1a[10], wW1b[10], wU1a[10], wU1b[10];
#pragma unroll
    for (int m = 0; m < 10; m++) {
        int k0 = 2 * m * H3, k1 = (2 * m + 1) * H3;
        if (act) {
            wU0a[m] = pack2(U0[k0 + c1], U0[k1 + c1]);
            wU0b[m] = pack2(U0[k0 + c2], U0[k1 + c2]);
            wW1a[m] = pack2(W1[k0 + c1], W1[k1 + c1]);
            wW1b[m] = pack2(W1[k0 + c2], W1[k1 + c2]);
            wU1a[m] = pack2(U1[k0 + c1], U1[k1 + c1]);
            wU1b[m] = pack2(U1[k0 + c2], U1[k1 + c2]);
        } else {
            wU0a[m] = wU0b[m] = wW1a[m] = wW1b[m] = wU1a[m] = wU1b[m] = 0ull;
        }
    }
    const float bU0a = act ? b0r[c1] : 0.f, bU0b = act ? b0r[c2] : 0.f;
    const float bW1a = act ? b1i[c1] : 0.f, bW1b = act ? b1i[c2] : 0.f;
    const float bU1a = act ? b1r[c1] : 0.f, bU1b = act ? b1r[c2] : 0.f;

    // ---- state: two independent elements A,B ----
    u64 hpA0[10], hpA1[10], hpB0[10], hpB1[10];
#pragma unroll
    for (int m = 0; m < 10; m++) { hpA0[m] = hpA1[m] = hpB0[m] = hpB1[m] = 0ull; }
    float hoA0 = 0.f, hoA1 = 0.f, hoB0 = 0.f, hoB1 = 0.f;

    const int* xrowA = x + e0 * TSTEPS;
    const int* xrowB = xrowA + TSTEPS;

    int xiA = __ldg(xrowA + 0), xiB = __ldg(xrowB + 0);
    float2 xwA = *reinterpret_cast<const float2*>(W0pad + xiA * WPAD + 2 * lane);
    float2 xwB = *reinterpret_cast<const float2*>(W0pad + xiB * WPAD + 2 * lane);
    xiA = __ldg(xrowA + 1); xiB = __ldg(xrowB + 1);

    // rotated-pipeline carried values: recurrent matvec results for step t
    // (h = 0 initially -> matvec result is just the bias)
    float r0aA = bU0a, r0bA = bU0b, r0aB = bU0a, r0bB = bU0b;
    float r1aA = bU1a, r1bA = bU1b, r1aB = bU1a, r1bB = bU1b;

#pragma unroll 1
    for (int t = 0; t < TSTEPS; t++) {
        float2 xwnA = *reinterpret_cast<const float2*>(W0pad + xiA * WPAD + 2 * lane);
        float2 xwnB = *reinterpret_cast<const float2*>(W0pad + xiB * WPAD + 2 * lane);
        int tn = (t + 2 < TSTEPS) ? t + 2 : TSTEPS - 1;
        xiA = __ldg(xrowA + tn); xiB = __ldg(xrowB + tn);

        // ---- layer-0 gates for step t (r0 carried in) ----
        gates(xwA.x + r0aA, xwA.y + r0bA, xwA.y, r0bA, lane, hoA0);
        gates(xwB.x + r0aB, xwB.y + r0bB, xwB.y, r0bB, lane, hoB0);
        if (lane < H) { hA0s[lane] = hoA0; hB0s[lane] = hoB0; }
        __syncwarp();
        ld_h(hA0s, hpA0);
        ld_h(hB0s, hpB0);

        // ---- consumers of h0(t): W1 (layer-1 input, this step) and U0 (recurrence, t+1)
        float q1A, q2A, q1B, q2B;
        matvec(wW1a, wW1b, bW1a, bW1b, hpA0, q1A, q2A);
        matvec(wW1a, wW1b, bW1a, bW1b, hpB0, q1B, q2B);
        matvec(wU0a, wU0b, bU0a, bU0b, hpA0, r0aA, r0bA);   // r0 for t+1 — hides gates1 latency
        matvec(wU0a, wU0b, bU0a, bU0b, hpB0, r0aB, r0bB);

        // ---- layer-1 gates for step t (r1 carried in) ----
        gates(q1A + r1aA, q2A + r1bA, q2A, r1bA, lane, hoA1);
        gates(q1B + r1aB, q2B + r1bB, q2B, r1bB, lane, hoB1);
        if (lane < H) { hA1s[lane] = hoA1; hB1s[lane] = hoB1; }
        __syncwarp();
        ld_h(hA1s, hpA1);
        ld_h(hB1s, hpB1);

        // ---- U1 recurrence for t+1 — hides next step's gates0 latency ----
        matvec(wU1a, wU1b, bU1a, bU1b, hpA1, r1aA, r1bA);
        matvec(wU1a, wU1b, bU1a, bU1b, hpB1, r1aB, r1bB);

        xwA = xwnA; xwB = xwnB;
    }

    // ---- softmax(h1 @ Wd + bd) per element; lane c<15 owns logit c ----
#pragma unroll
    for (int el = 0; el < 2; el++) {
        const u64* hp = el ? hpB1 : hpA1;
        float lg = -CUDART_INF_F;
        if (lane < LOUT) {
            lg = bd[lane];
#pragma unroll
            for (int m = 0; m < 10; m++) {
                float ha, hb;
                unp(hp[m], ha, hb);
                lg = fmaf(ha, Wd[(2 * m) * LOUT + lane], lg);
                lg = fmaf(hb, Wd[(2 * m + 1) * LOUT + lane], lg);
            }
        }
        float mx = lg;
#pragma unroll
        for (int d = 8; d >= 1; d >>= 1) mx = fmaxf(mx, __shfl_xor_sync(F, mx, d));
        float p = __expf(lg - mx);
        float sm = p;
#pragma unroll
        for (int d = 8; d >= 1; d >>= 1) sm += __shfl_xor_sync(F, sm, d);
        if (lane < LOUT) out[(e0 + el) * LOUT + lane] = __fdividef(p, sm);
    }
}

extern "C" void kernel_launch(void* const* d_in, const int* in_sizes, int n_in,
                              void* d_out, int out_size) {
    const int*   x   = (const int*)d_in[0];
    const float* W0  = (const float*)d_in[1];
    const float* U0  = (const float*)d_in[2];
    const float* b0i = (const float*)d_in[3];
    const float* b0r = (const float*)d_in[4];
    const float* W1  = (const float*)d_in[5];
    const float* U1  = (const float*)d_in[6];
    const float* b1i = (const float*)d_in[7];
    const float* b1r = (const float*)d_in[8];
    const float* Wd  = (const float*)d_in[9];
    const float* bd  = (const float*)d_in[10];
    // d_in[11] = drop_rate (identity), unused

    prep_w0<<<64, 256>>>(W0, b0i);
    gru2_kernel<<<NB / 8, 128>>>(x, U0, b0r, W1, U1, b1i, b1r, Wd, bd, (float*)d_out);
}

// round 17
// speedup vs baseline: 1.3552x; 1.0481x over previous
#include <cuda_runtime.h>
#include <math_constants.h>

#define H        20
#define H3       60
#define NB       2048
#define LOUT     15
#define TSTEPS   128
#define WPAD     64      // padded W0 row (floats)

typedef unsigned long long u64;

// bias-folded, lane-interleaved W0 gather table: [V=256][64]
// slot 2l = col l, slot 2l+1 = col 30+l (l<30); slots 60..63 = 0
__device__ float W0pad[256 * WPAD];

__device__ __forceinline__ u64 pack2(float a, float b) {
    u64 r; asm("mov.b64 %0,{%1,%2};" : "=l"(r) : "f"(a), "f"(b)); return r;
}
__device__ __forceinline__ u64 mk2(float a, float b) {
    float2 f = make_float2(a, b);
    return *reinterpret_cast<u64*>(&f);
}
__device__ __forceinline__ u64 ffma2(u64 a, u64 b, u64 c) {
    u64 d; asm("fma.rn.f32x2 %0,%1,%2,%3;" : "=l"(d) : "l"(a), "l"(b), "l"(c)); return d;
}
__device__ __forceinline__ void unp(u64 p, float& lo, float& hi) {
    float2 f = *reinterpret_cast<float2*>(&p);
    lo = f.x; hi = f.y;
}
__device__ __forceinline__ float tanh_fast(float x) {
    float y; asm("tanh.approx.f32 %0,%1;" : "=f"(y) : "f"(x)); return y;
}
__device__ __forceinline__ float sigm_fast(float x) {   // 0.5 + 0.5*tanh(x/2)
    return fmaf(0.5f, tanh_fast(0.5f * x), 0.5f);
}

__global__ void prep_w0(const float* __restrict__ W0, const float* __restrict__ b0i) {
    int idx = blockIdx.x * 256 + threadIdx.x;      // 16384 = 256*64
    int v = idx >> 6, sl = idx & 63;
    int l = sl >> 1;
    int c = (sl & 1) ? 30 + l : l;
    float val = 0.f;
    if (l < 30) val = W0[v * H3 + c] + b0i[c];
    W0pad[idx] = val;
}

// acc over k-pairs; scalar bias post-add
__device__ __forceinline__ void matvec(const u64 wa[10], const u64 wb[10],
                                       float biasA, float biasB, const u64 hp[10],
                                       float& r1, float& r2) {
    u64 aA = 0ull, aB = 0ull;
#pragma unroll
    for (int m = 0; m < 10; m++) {
        aA = ffma2(hp[m], wa[m], aA);
        aB = ffma2(hp[m], wb[m], aB);
    }
    float lo, hi;
    unp(aA, lo, hi); r1 = (lo + hi) + biasA;
    unp(aB, lo, hi); r2 = (lo + hi) + biasB;
}

// one GRU gate-exchange + update for the 2-col-per-lane layout (unit i = lane, i<20)
__device__ __forceinline__ void gates(float s1, float s2, float x2, float r2v,
                                      int lane, float& ho) {
    const unsigned F = 0xFFFFFFFFu;
    float ra = __shfl_sync(F, s1, 20 + lane);
    float rb = __shfl_sync(F, s2, lane - 10);
    float rr = (lane < 10) ? ra : rb;
    float xh = __shfl_sync(F, x2, 10 + lane);
    float rh = __shfl_sync(F, r2v, 10 + lane);
    float z  = sigm_fast(s1);
    float rg = sigm_fast(rr);
    float hh = tanh_fast(fmaf(rg, rh, xh));
    ho = z * (ho - hh) + hh;
}

// SMEM broadcast reload: 20 floats -> 10 k-pair u64 via 5x LDS.128
__device__ __forceinline__ void ld_h(const float* __restrict__ p, u64 hp[10]) {
#pragma unroll
    for (int i = 0; i < 5; i++) {
        float4 f = *reinterpret_cast<const float4*>(p + 4 * i);
        hp[2 * i]     = mk2(f.x, f.y);
        hp[2 * i + 1] = mk2(f.z, f.w);
    }
}

__global__ void __launch_bounds__(128, 2)
gru2_kernel(const int* __restrict__ x,
            const float* __restrict__ U0, const float* __restrict__ b0r,
            const float* __restrict__ W1, const float* __restrict__ U1,
            const float* __restrict__ b1i, const float* __restrict__ b1r,
            const float* __restrict__ Wd, const float* __restrict__ bd,
            float* __restrict__ out)
{
    // double-buffered h scratch: [buf][warp][slot: A0,B0,A1,B1][20]
    __shared__ __align__(16) float hsm[2][4][4][20];

    const unsigned F = 0xFFFFFFFFu;
    const int lane = threadIdx.x & 31;
    const int w = threadIdx.x >> 5;
    const int e0 = (blockIdx.x * 4 + w) * 2;           // two elements per warp
    const bool act = lane < 30;
    const int c1 = lane, c2 = act ? 30 + lane : 30;

    // ---- weights into registers (shared by both elements) ----
    u64 wU0a[10], wU0b[10], wW1a[10], wW1b[10], wU1a[10], wU1b[10];
#pragma unroll
    for (int m = 0; m < 10; m++) {
        int k0 = 2 * m * H3, k1 = (2 * m + 1) * H3;
        if (act) {
            wU0a[m] = pack2(U0[k0 + c1], U0[k1 + c1]);
            wU0b[m] = pack2(U0[k0 + c2], U0[k1 + c2]);
            wW1a[m] = pack2(W1[k0 + c1], W1[k1 + c1]);
            wW1b[m] = pack2(W1[k0 + c2], W1[k1 + c2]);
            wU1a[m] = pack2(U1[k0 + c1], U1[k1 + c1]);
            wU1b[m] = pack2(U1[k0 + c2], U1[k1 + c2]);
        } else {
            wU0a[m] = wU0b[m] = wW1a[m] = wW1b[m] = wU1a[m] = wU1b[m] = 0ull;
        }
    }
    const float bU0a = act ? b0r[c1] : 0.f, bU0b = act ? b0r[c2] : 0.f;
    const float bW1a = act ? b1i[c1] : 0.f, bW1b = act ? b1i[c2] : 0.f;
    const float bU1a = act ? b1r[c1] : 0.f, bU1b = act ? b1r[c2] : 0.f;

    // ---- state ----
    u64 hpA0[10], hpA1[10], hpB0[10], hpB1[10];
#pragma unroll
    for (int m = 0; m < 10; m++) { hpA0[m] = hpA1[m] = hpB0[m] = hpB1[m] = 0ull; }
    float hoA0 = 0.f, hoA1 = 0.f, hoB0 = 0.f, hoB1 = 0.f;

    const int* xrowA = x + e0 * TSTEPS;
    const int* xrowB = xrowA + TSTEPS;

    int xiA = __ldg(xrowA + 0), xiB = __ldg(xrowB + 0);
    float2 xwA = *reinterpret_cast<const float2*>(W0pad + xiA * WPAD + 2 * lane);
    float2 xwB = *reinterpret_cast<const float2*>(W0pad + xiB * WPAD + 2 * lane);
    xiA = __ldg(xrowA + 1); xiB = __ldg(xrowB + 1);

    // two-stage pipeline carries:
    //   r0 = U0@h0(t-1)+b0r   (layer-0 recurrence for step t)   -> bias at t=0 (h0=0)
    //   q  = W1@h0(t-1)+b1i   (layer-1 input for step t-1)      -> 0 at t=0 (virtual step)
    //   r1 = U1@h1(t-2)+b1r   (layer-1 recurrence for step t-1) -> 0 at t=0 (virtual step)
    // With q=r1=0 the virtual gates1 yields exactly h1(-1)=0 (z=.5, hh=tanh(0+.5*0)=0).
    float r0aA = bU0a, r0bA = bU0b, r0aB = bU0a, r0bB = bU0b;
    float q1A = 0.f, q2A = 0.f, q1B = 0.f, q2B = 0.f;
    float r1aA = 0.f, r1bA = 0.f, r1aB = 0.f, r1bB = 0.f;

#pragma unroll 1
    for (int t = 0; t < TSTEPS; t++) {
        float2 xwnA = *reinterpret_cast<const float2*>(W0pad + xiA * WPAD + 2 * lane);
        float2 xwnB = *reinterpret_cast<const float2*>(W0pad + xiB * WPAD + 2 * lane);
        int tn = (t + 2 < TSTEPS) ? t + 2 : TSTEPS - 1;
        xiA = __ldg(xrowA + tn); xiB = __ldg(xrowB + tn);

        // ---- 4 independent gate chains: layer0 @ t, layer1 @ t-1 ----
        gates(xwA.x + r0aA, xwA.y + r0bA, xwA.y, r0bA, lane, hoA0);
        gates(xwB.x + r0aB, xwB.y + r0bB, xwB.y, r0bB, lane, hoB0);
        gates(q1A + r1aA, q2A + r1bA, q2A, r1bA, lane, hoA1);
        gates(q1B + r1aB, q2B + r1bB, q2B, r1bB, lane, hoB1);

        // ---- single publish point (double-buffered) ----
        float* hb = &hsm[t & 1][w][0][0];
        if (lane < H) {
            hb[lane]      = hoA0;
            hb[20 + lane] = hoB0;
            hb[40 + lane] = hoA1;
            hb[60 + lane] = hoB1;
        }
        __syncwarp();
        ld_h(hb,      hpA0);
        ld_h(hb + 20, hpB0);
        ld_h(hb + 40, hpA1);
        ld_h(hb + 60, hpB1);

        // ---- 6 independent matvecs feed the next iteration ----
        matvec(wW1a, wW1b, bW1a, bW1b, hpA0, q1A, q2A);     // q(t)
        matvec(wW1a, wW1b, bW1a, bW1b, hpB0, q1B, q2B);
        matvec(wU0a, wU0b, bU0a, bU0b, hpA0, r0aA, r0bA);   // r0(t+1)
        matvec(wU0a, wU0b, bU0a, bU0b, hpB0, r0aB, r0bB);
        matvec(wU1a, wU1b, bU1a, bU1b, hpA1, r1aA, r1bA);   // r1(t)
        matvec(wU1a, wU1b, bU1a, bU1b, hpB1, r1aB, r1bB);

        xwA = xwnA; xwB = xwnB;
    }

    // ---- epilogue: layer-1 gates for the final step (t = T-1) ----
    gates(q1A + r1aA, q2A + r1bA, q2A, r1bA, lane, hoA1);
    gates(q1B + r1aB, q2B + r1bB, q2B, r1bB, lane, hoB1);
    {
        float* hb = &hsm[0][w][0][0];
        if (lane < H) { hb[40 + lane] = hoA1; hb[60 + lane] = hoB1; }
        __syncwarp();
        ld_h(hb + 40, hpA1);
        ld_h(hb + 60, hpB1);
    }

    // ---- softmax(h1 @ Wd + bd) per element; lane c<15 owns logit c ----
#pragma unroll
    for (int el = 0; el < 2; el++) {
        const u64* hp = el ? hpB1 : hpA1;
        float lg = -CUDART_INF_F;
        if (lane < LOUT) {
            lg = bd[lane];
#pragma unroll
            for (int m = 0; m < 10; m++) {
                float ha, hb2;
                unp(hp[m], ha, hb2);
                lg = fmaf(ha, Wd[(2 * m) * LOUT + lane], lg);
                lg = fmaf(hb2, Wd[(2 * m + 1) * LOUT + lane], lg);
            }
        }
        float mx = lg;
#pragma unroll
        for (int d = 8; d >= 1; d >>= 1) mx = fmaxf(mx, __shfl_xor_sync(F, mx, d));
        float p = __expf(lg - mx);
        float sm = p;
#pragma unroll
        for (int d = 8; d >= 1; d >>= 1) sm += __shfl_xor_sync(F, sm, d);
        if (lane < LOUT) out[(e0 + el) * LOUT + lane] = __fdividef(p, sm);
    }
}

extern "C" void kernel_launch(void* const* d_in, const int* in_sizes, int n_in,
                              void* d_out, int out_size) {
    const int*   x   = (const int*)d_in[0];
    const float* W0  = (const float*)d_in[1];
    const float* U0  = (const float*)d_in[2];
    const float* b0i = (const float*)d_in[3];
    const float* b0r = (const float*)d_in[4];
    const float* W1  = (const float*)d_in[5];
    const float* U1  = (const float*)d_in[6];
    const float* b1i = (const float*)d_in[7];
    const float* b1r = (const float*)d_in[8];
    const float* Wd  = (const float*)d_in[9];
    const float* bd  = (const float*)d_in[10];
    // d_in[11] = drop_rate (identity), unused

    prep_w0<<<64, 256>>>(W0, b0i);
    gru2_kernel<<<NB / 8, 128>>>(x, U0, b0r, W1, U1, b1i, b1r, Wd, bd, (float*)d_out);
}